// round 13
// baseline (speedup 1.0000x reference)
#include <cuda_runtime.h>
#include <math_constants.h>
#include <cstdint>

// Problem constants
#define S_LEN   4096
#define D_MODEL 512
#define H_NUM   8
#define HD      64
#define LDQKV   1536      // 3*D_MODEL

// Q pre-scale: 1/sqrt(64) * log2(e)  (softmax runs in exp2 domain)
#define Q_PRESCALE 0.18033688011112042f

// Scratch (no cudaMalloc allowed)
__device__ float g_qkv[S_LEN * LDQKV];      // [4096,1536] Q|K|V (tf32, Q pre-scaled)
__device__ float g_attn[S_LEN * D_MODEL];   // [4096,512]  attention out (tf32-rounded)
__device__ float g_qr [S_LEN * D_MODEL];    // query, tf32-rounded
__device__ float g_wi [3 * D_MODEL * D_MODEL]; // in_proj_weight, tf32-rounded
__device__ float g_wo [D_MODEL * D_MODEL];  // out_proj_weight, tf32-rounded

// ---------------------------------------------------------------------------
// Helpers
// ---------------------------------------------------------------------------
__device__ __forceinline__ uint32_t f2tf32(float x) {
    uint32_t r;
    asm("cvt.rna.tf32.f32 %0, %1;" : "=r"(r) : "f"(x));
    return r;
}

__device__ __forceinline__ float ex2f(float x) {
    float y;
    asm("ex2.approx.ftz.f32 %0, %1;" : "=f"(y) : "f"(x));
    return y;
}

__device__ __forceinline__ void mma_tf32(float d[4], const uint32_t a[4],
                                         const uint32_t b[2], const float c[4]) {
    asm volatile(
        "mma.sync.aligned.m16n8k8.row.col.f32.tf32.tf32.f32 "
        "{%0,%1,%2,%3}, {%4,%5,%6,%7}, {%8,%9}, {%10,%11,%12,%13};"
        : "=f"(d[0]), "=f"(d[1]), "=f"(d[2]), "=f"(d[3])
        : "r"(a[0]), "r"(a[1]), "r"(a[2]), "r"(a[3]),
          "r"(b[0]), "r"(b[1]),
          "f"(c[0]), "f"(c[1]), "f"(c[2]), "f"(c[3]));
}

__device__ __forceinline__ uint32_t smem_u32(const void* p) {
    uint32_t a;
    asm("{ .reg .u64 t; cvta.to.shared.u64 t, %1; cvt.u32.u64 %0, t; }"
        : "=r"(a) : "l"(p));
    return a;
}

// cp.async.ca: 16B gmem->smem, L1-preserving (the .cg variant regressed in R4)
__device__ __forceinline__ void cp_async16(uint32_t dst, const void* src) {
    asm volatile("cp.async.ca.shared.global [%0], [%1], 16;"
                 :: "r"(dst), "l"(src));
}
#define CP_COMMIT()  asm volatile("cp.async.commit_group;")
#define CP_WAIT0()   asm volatile("cp.async.wait_group 0;")

// ---------------------------------------------------------------------------
// Elementwise tf32 rounding pass (src -> dst), float4 granular.
// ---------------------------------------------------------------------------
__global__ void round_tf32_kernel(const float* __restrict__ src,
                                  float* __restrict__ dst, int n4) {
    int i = blockIdx.x * blockDim.x + threadIdx.x;
    if (i < n4) {
        float4 v = *(const float4*)(src + 4 * i);
        v.x = __uint_as_float(f2tf32(v.x));
        v.y = __uint_as_float(f2tf32(v.y));
        v.z = __uint_as_float(f2tf32(v.z));
        v.w = __uint_as_float(f2tf32(v.w));
        *(float4*)(dst + 4 * i) = v;
    }
}

// ---------------------------------------------------------------------------
// tf32 tensor-core GEMM: C[M,N] = A[M,K] @ B[N,K]^T + bias[N]
// Inputs ALREADY tf32-valued; staging via cp.async.ca double buffer.
// qkv_round=1: epilogue scales Q columns (<512) by Q_PRESCALE + rounds all
// outputs to tf32 so the flash kernel stages with raw copies.
// ---------------------------------------------------------------------------
#define GLD 36
#define GEMM_SMEM (2 * 2 * 128 * GLD * 4)   // 73728 bytes

__global__ void __launch_bounds__(256, 2) gemm_tf32_bias(
    const float* __restrict__ A, const float* __restrict__ B,
    const float* __restrict__ bias, float* __restrict__ C,
    int M, int N, int K, int qkv_round)
{
    extern __shared__ float sm[];
    float* As[2] = { sm,                 sm + 128 * GLD     };
    float* Bs[2] = { sm + 2 * 128 * GLD, sm + 3 * 128 * GLD };

    const int tid  = threadIdx.x;
    const int lane = tid & 31;
    const int wid  = tid >> 5;
    const int qc   = lane & 3;
    const int qg   = lane >> 2;
    const int wm   = (wid & 3) * 32;
    const int wn   = (wid >> 2) * 64;
    const int m0   = blockIdx.y * 128;
    const int n0   = blockIdx.x * 128;

    uint32_t as_addr[2][4], bs_addr[2][4];
#pragma unroll
    for (int i = 0; i < 4; i++) {
        int f   = tid + i * 256;
        int row = f >> 3;
        int c4  = (f & 7) << 2;
        as_addr[0][i] = smem_u32(As[0] + row * GLD + c4);
        as_addr[1][i] = smem_u32(As[1] + row * GLD + c4);
        bs_addr[0][i] = smem_u32(Bs[0] + row * GLD + c4);
        bs_addr[1][i] = smem_u32(Bs[1] + row * GLD + c4);
    }

    float acc[2][8][4];
#pragma unroll
    for (int mf = 0; mf < 2; mf++)
#pragma unroll
        for (int nf = 0; nf < 8; nf++)
#pragma unroll
            for (int j = 0; j < 4; j++) acc[mf][nf][j] = 0.0f;

    const int nt = K / 32;

    // prologue: stage tile 0
#pragma unroll
    for (int i = 0; i < 4; i++) {
        int f   = tid + i * 256;
        int row = f >> 3;
        int c4  = (f & 7) << 2;
        cp_async16(as_addr[0][i], A + (size_t)(m0 + row) * K + c4);
        cp_async16(bs_addr[0][i], B + (size_t)(n0 + row) * K + c4);
    }
    CP_COMMIT();
    CP_WAIT0();
    __syncthreads();

    for (int t = 0; t < nt; t++) {
        const int cur = t & 1;
        if (t + 1 < nt) {
            const int nxt = cur ^ 1;
            int k0 = (t + 1) * 32;
#pragma unroll
            for (int i = 0; i < 4; i++) {
                int f   = tid + i * 256;
                int row = f >> 3;
                int c4  = (f & 7) << 2;
                cp_async16(as_addr[nxt][i], A + (size_t)(m0 + row) * K + k0 + c4);
                cp_async16(bs_addr[nxt][i], B + (size_t)(n0 + row) * K + k0 + c4);
            }
            CP_COMMIT();
        }

        const float* as = As[cur];
        const float* bs = Bs[cur];
#pragma unroll
        for (int kc = 0; kc < 4; kc++) {
            uint32_t bfr[8][2];
#pragma unroll
            for (int nf = 0; nf < 8; nf++) {
                const float* bp = bs + (wn + nf * 8 + qg) * GLD + kc * 8 + qc;
                bfr[nf][0] = __float_as_uint(bp[0]);
                bfr[nf][1] = __float_as_uint(bp[4]);
            }
#pragma unroll
            for (int mf = 0; mf < 2; mf++) {
                const float* ap = as + (wm + mf * 16 + qg) * GLD + kc * 8 + qc;
                uint32_t afr[4];
                afr[0] = __float_as_uint(ap[0]);
                afr[1] = __float_as_uint(ap[8 * GLD]);
                afr[2] = __float_as_uint(ap[4]);
                afr[3] = __float_as_uint(ap[8 * GLD + 4]);
#pragma unroll
                for (int nf = 0; nf < 8; nf++)
                    mma_tf32(acc[mf][nf], afr, bfr[nf], acc[mf][nf]);
            }
        }

        CP_WAIT0();
        __syncthreads();
    }

#pragma unroll
    for (int mf = 0; mf < 2; mf++) {
        int row0 = m0 + wm + mf * 16 + qg;
#pragma unroll
        for (int nf = 0; nf < 8; nf++) {
            int col = n0 + wn + nf * 8 + 2 * qc;
            float b0 = bias[col], b1 = bias[col + 1];
            float2 v0 = make_float2(acc[mf][nf][0] + b0, acc[mf][nf][1] + b1);
            float2 v1 = make_float2(acc[mf][nf][2] + b0, acc[mf][nf][3] + b1);
            if (qkv_round) {
                float sc = (col < D_MODEL) ? Q_PRESCALE : 1.0f;  // scale Q only
                v0.x = __uint_as_float(f2tf32(v0.x * sc));
                v0.y = __uint_as_float(f2tf32(v0.y * sc));
                v1.x = __uint_as_float(f2tf32(v1.x * sc));
                v1.y = __uint_as_float(f2tf32(v1.y * sc));
            }
            *(float2*)(C + (size_t)row0 * N + col)       = v0;
            *(float2*)(C + (size_t)(row0 + 8) * N + col) = v1;
        }
    }
}

// ---------------------------------------------------------------------------
// Flash attention, tf32 mma, Br=128 / Bc=64 / Hd=64, 4 warps, 32 q-rows/warp.
// R10 loop body (kc-outer shared fragments, scalar LDS, exp2 softmax) with
// ONE structural change, tested in isolation: K/V double buffered, tile t+1
// staged between softmax and PV of tile t, ONE __syncthreads per tile
// (staging latency hidden behind the PV mma phase).
// Hazards: tile t reads buf / stages buf^1; end-of-tile barrier separates
// t's buf reads from t+1's staging of buf. Q-frag reads and P stores touch
// only warp-private rows -> __syncwarp suffices there.
// ---------------------------------------------------------------------------
#define LDA 68
#define LDB 72
// Ks x2 + Vs x2 + Ps[128]: (2*64*68 + 2*64*72 + 128*68)*4 = 106496 B
#define FLASH_SMEM ((2 * 64 * LDA + 2 * 64 * LDB + 128 * LDA) * 4)

__global__ void __launch_bounds__(128, 2) flash_mma_kernel(
    const float* __restrict__ qkv, float* __restrict__ attn_out)
{
    extern __shared__ float sm[];
    float* Ksb[2] = { sm,                sm + 64 * LDA };
    float* Vsb[2] = { sm + 2 * 64 * LDA, sm + 2 * 64 * LDA + 64 * LDB };
    float* Ps = sm + 2 * 64 * LDA + 2 * 64 * LDB;   // [128][LDA] (Q staging, then P)

    const int tid  = threadIdx.x;
    const int lane = tid & 31;
    const int wid  = tid >> 5;
    const int qc   = lane & 3;
    const int qg   = lane >> 2;
    const int h    = blockIdx.y;
    const int q0   = blockIdx.x * 128;
    const int colb = h * HD;

    const int srow = tid >> 4;          // staging row 0..7 (stride 8)
    const int sc4  = (tid & 15) << 2;   // staging col 0..60

    // ---- Stage Q tile (pre-scaled, pre-rounded): raw copy into Ps ----
#pragma unroll
    for (int i = 0; i < 16; i++) {
        int f   = tid + i * 128;
        int row = f >> 4;
        int c4  = (f & 15) << 2;
        *(float4*)(Ps + row * LDA + c4) =
            *(const float4*)(qkv + (size_t)(q0 + row) * LDQKV + colb + c4);
    }
    // ---- Stage KV tile 0 into buf 0 ----
    {
        const float* kb = qkv + (size_t)srow * LDQKV + colb + D_MODEL + sc4;
#pragma unroll
        for (int r = 0; r < 8; r++) {
            *(float4*)(Ksb[0] + (srow + r * 8) * LDA + sc4) =
                *(const float4*)(kb + (size_t)(r * 8) * LDQKV);
            *(float4*)(Vsb[0] + (srow + r * 8) * LDB + sc4) =
                *(const float4*)(kb + (size_t)(r * 8) * LDQKV + D_MODEL);
        }
    }
    __syncthreads();

    // ---- Q fragments to registers: 2 m-frags x 8 k-chunks ----
    // (reads only this warp's 32 rows of Ps; later P stores hit the same
    //  warp-private rows, so no extra barrier is needed)
    uint32_t qf[2][8][4];
#pragma unroll
    for (int mf = 0; mf < 2; mf++) {
        const int r0 = wid * 32 + mf * 16 + qg;
#pragma unroll
        for (int kc = 0; kc < 8; kc++) {
            int d0 = kc * 8;
            qf[mf][kc][0] = __float_as_uint(Ps[r0 * LDA + d0 + qc]);
            qf[mf][kc][1] = __float_as_uint(Ps[(r0 + 8) * LDA + d0 + qc]);
            qf[mf][kc][2] = __float_as_uint(Ps[r0 * LDA + d0 + qc + 4]);
            qf[mf][kc][3] = __float_as_uint(Ps[(r0 + 8) * LDA + d0 + qc + 4]);
        }
    }

    float o[2][8][4];
#pragma unroll
    for (int mf = 0; mf < 2; mf++)
#pragma unroll
        for (int nt = 0; nt < 8; nt++)
#pragma unroll
            for (int j = 0; j < 4; j++) o[mf][nt][j] = 0.0f;
    float m_run[2][2] = { {-CUDART_INF_F, -CUDART_INF_F},
                          {-CUDART_INF_F, -CUDART_INF_F} };
    float l_run[2][2] = { {0.f, 0.f}, {0.f, 0.f} };

    const int NT = S_LEN / 64;
    for (int t = 0; t < NT; t++) {
        const int buf = t & 1;
        const float* Ks = Ksb[buf];
        const float* Vs = Vsb[buf];

        // ---- S = Q K^T, kc-outer: K B-frags loaded once, shared by both mf ----
        float s[2][8][4];
#pragma unroll
        for (int mf = 0; mf < 2; mf++)
#pragma unroll
            for (int nt = 0; nt < 8; nt++)
#pragma unroll
                for (int j = 0; j < 4; j++) s[mf][nt][j] = 0.0f;

#pragma unroll
        for (int kc = 0; kc < 8; kc++) {
            uint32_t bfr[8][2];
#pragma unroll
            for (int nt = 0; nt < 8; nt++) {
                const float* kb = Ks + (nt * 8 + qg) * LDA + kc * 8 + qc;
                bfr[nt][0] = __float_as_uint(kb[0]);
                bfr[nt][1] = __float_as_uint(kb[4]);
            }
#pragma unroll
            for (int mf = 0; mf < 2; mf++)
#pragma unroll
                for (int nt = 0; nt < 8; nt++)
                    mma_tf32(s[mf][nt], qf[mf][kc], bfr[nt], s[mf][nt]);
        }

        // ---- Online softmax per m-fragment (exp2 domain), store P ----
#pragma unroll
        for (int mf = 0; mf < 2; mf++) {
            const int r0 = wid * 32 + mf * 16 + qg;
            const int r1 = r0 + 8;

            float mlo = -CUDART_INF_F, mhi = -CUDART_INF_F;
#pragma unroll
            for (int nt = 0; nt < 8; nt++) {
                mlo = fmaxf(mlo, fmaxf(s[mf][nt][0], s[mf][nt][1]));
                mhi = fmaxf(mhi, fmaxf(s[mf][nt][2], s[mf][nt][3]));
            }
            mlo = fmaxf(mlo, __shfl_xor_sync(0xffffffffu, mlo, 1));
            mlo = fmaxf(mlo, __shfl_xor_sync(0xffffffffu, mlo, 2));
            mhi = fmaxf(mhi, __shfl_xor_sync(0xffffffffu, mhi, 1));
            mhi = fmaxf(mhi, __shfl_xor_sync(0xffffffffu, mhi, 2));

            float mnlo = fmaxf(m_run[mf][0], mlo);
            float mnhi = fmaxf(m_run[mf][1], mhi);
            float alo  = ex2f(m_run[mf][0] - mnlo);   // 0 on first tile
            float ahi  = ex2f(m_run[mf][1] - mnhi);
            m_run[mf][0] = mnlo; m_run[mf][1] = mnhi;

            float tlo = 0.0f, thi = 0.0f;
#pragma unroll
            for (int nt = 0; nt < 8; nt++) {
                float p0 = ex2f(s[mf][nt][0] - mnlo);
                float p1 = ex2f(s[mf][nt][1] - mnlo);
                float p2 = ex2f(s[mf][nt][2] - mnhi);
                float p3 = ex2f(s[mf][nt][3] - mnhi);
                tlo += p0 + p1;
                thi += p2 + p3;
                uint2 plo = make_uint2(f2tf32(p0), f2tf32(p1));
                uint2 phi = make_uint2(f2tf32(p2), f2tf32(p3));
                *(uint2*)(Ps + r0 * LDA + nt * 8 + 2 * qc) = plo;
                *(uint2*)(Ps + r1 * LDA + nt * 8 + 2 * qc) = phi;
            }
            tlo += __shfl_xor_sync(0xffffffffu, tlo, 1);
            tlo += __shfl_xor_sync(0xffffffffu, tlo, 2);
            thi += __shfl_xor_sync(0xffffffffu, thi, 1);
            thi += __shfl_xor_sync(0xffffffffu, thi, 2);
            l_run[mf][0] = l_run[mf][0] * alo + tlo;
            l_run[mf][1] = l_run[mf][1] * ahi + thi;

#pragma unroll
            for (int nt = 0; nt < 8; nt++) {
                o[mf][nt][0] *= alo; o[mf][nt][1] *= alo;
                o[mf][nt][2] *= ahi; o[mf][nt][3] *= ahi;
            }
        }

        __syncwarp();   // P rows are warp-private; order STS before LDS

        // ---- Stage KV tile t+1 into buf^1 (latency hidden behind PV) ----
        if (t + 1 < NT) {
            const float* kb = qkv + (size_t)((t + 1) * 64 + srow) * LDQKV
                            + colb + D_MODEL + sc4;
            float* Kn = Ksb[buf ^ 1];
            float* Vn = Vsb[buf ^ 1];
#pragma unroll
            for (int r = 0; r < 8; r++) {
                *(float4*)(Kn + (srow + r * 8) * LDA + sc4) =
                    *(const float4*)(kb + (size_t)(r * 8) * LDQKV);
                *(float4*)(Vn + (srow + r * 8) * LDB + sc4) =
                    *(const float4*)(kb + (size_t)(r * 8) * LDQKV + D_MODEL);
            }
        }

        // ---- O += P V  (kc-outer: V B-frags shared by both m-frags) ----
#pragma unroll
        for (int kc = 0; kc < 8; kc++) {
            uint32_t vfr[8][2];
#pragma unroll
            for (int nt = 0; nt < 8; nt++) {
                vfr[nt][0] = __float_as_uint(Vs[(kc * 8 + qc) * LDB + nt * 8 + qg]);
                vfr[nt][1] = __float_as_uint(Vs[(kc * 8 + qc + 4) * LDB + nt * 8 + qg]);
            }
#pragma unroll
            for (int mf = 0; mf < 2; mf++) {
                const int r0 = wid * 32 + mf * 16 + qg;
                const int r1 = r0 + 8;
                uint32_t a[4];
                a[0] = __float_as_uint(Ps[r0 * LDA + kc * 8 + qc]);
                a[1] = __float_as_uint(Ps[r1 * LDA + kc * 8 + qc]);
                a[2] = __float_as_uint(Ps[r0 * LDA + kc * 8 + qc + 4]);
                a[3] = __float_as_uint(Ps[r1 * LDA + kc * 8 + qc + 4]);
#pragma unroll
                for (int nt = 0; nt < 8; nt++)
                    mma_tf32(o[mf][nt], a, vfr[nt], o[mf][nt]);
            }
        }
        __syncthreads();   // buf reads + buf^1 staging writes complete
    }

    // ---- Epilogue: normalize + round to tf32 (out-proj stages raw) ----
#pragma unroll
    for (int mf = 0; mf < 2; mf++) {
        const int r0 = wid * 32 + mf * 16 + qg;
        const int r1 = r0 + 8;
        float ilo = 1.0f / l_run[mf][0];
        float ihi = 1.0f / l_run[mf][1];
#pragma unroll
        for (int nt = 0; nt < 8; nt++) {
            uint2 vlo = make_uint2(f2tf32(o[mf][nt][0] * ilo), f2tf32(o[mf][nt][1] * ilo));
            uint2 vhi = make_uint2(f2tf32(o[mf][nt][2] * ihi), f2tf32(o[mf][nt][3] * ihi));
            *(uint2*)(attn_out + (size_t)(q0 + r0) * D_MODEL + colb + nt * 8 + 2 * qc) = vlo;
            *(uint2*)(attn_out + (size_t)(q0 + r1) * D_MODEL + colb + nt * 8 + 2 * qc) = vhi;
        }
    }
}

// ---------------------------------------------------------------------------
// Launch: pre-round -> QKV proj -> flash -> out proj
// ---------------------------------------------------------------------------
extern "C" void kernel_launch(void* const* d_in, const int* in_sizes, int n_in,
                              void* d_out, int out_size)
{
    const float* query = (const float*)d_in[0];   // [1,4096,512]
    const float* w_in  = (const float*)d_in[1];   // [1536,512]
    const float* b_in  = (const float*)d_in[2];   // [1536]
    const float* w_out = (const float*)d_in[3];   // [512,512]
    const float* b_out = (const float*)d_in[4];   // [512]
    float*       out   = (float*)d_out;           // [1,4096,512]

    float *qkv, *attn, *qr, *wi, *wo;
    cudaGetSymbolAddress((void**)&qkv,  g_qkv);
    cudaGetSymbolAddress((void**)&attn, g_attn);
    cudaGetSymbolAddress((void**)&qr,   g_qr);
    cudaGetSymbolAddress((void**)&wi,   g_wi);
    cudaGetSymbolAddress((void**)&wo,   g_wo);

    cudaFuncSetAttribute(gemm_tf32_bias,
                         cudaFuncAttributeMaxDynamicSharedMemorySize, GEMM_SMEM);
    cudaFuncSetAttribute(flash_mma_kernel,
                         cudaFuncAttributeMaxDynamicSharedMemorySize, FLASH_SMEM);

    // 0) Pre-round inputs to tf32 (idempotent rounding copies)
    {
        int nq = S_LEN * D_MODEL / 4;          // 524288
        int ni = 3 * D_MODEL * D_MODEL / 4;    // 196608
        int no = D_MODEL * D_MODEL / 4;        // 65536
        round_tf32_kernel<<<(nq + 255) / 256, 256>>>(query, qr, nq);
        round_tf32_kernel<<<(ni + 255) / 256, 256>>>(w_in,  wi, ni);
        round_tf32_kernel<<<(no + 255) / 256, 256>>>(w_out, wo, no);
    }

    // 1) QKV projection (+ Q pre-scale incl. log2e + tf32 rounding)
    {
        dim3 grid(LDQKV / 128, S_LEN / 128);   // (12, 32)
        gemm_tf32_bias<<<grid, 256, GEMM_SMEM>>>(qr, wi, b_in, qkv,
                                                 S_LEN, LDQKV, D_MODEL, 1);
    }

    // 2) Flash attention per head (pipelined KV double-buffer)
    {
        dim3 grid(S_LEN / 128, H_NUM);   // (32, 8) = 256 CTAs
        flash_mma_kernel<<<grid, 128, FLASH_SMEM>>>(qkv, attn);
    }

    // 3) Output projection (full fp32 output)
    {
        dim3 grid(D_MODEL / 128, S_LEN / 128);  // (4, 32)
        gemm_tf32_bias<<<grid, 256, GEMM_SMEM>>>(attn, wo, b_out, out,
                                                 S_LEN, D_MODEL, D_MODEL, 0);
    }
}

// round 14
// speedup vs baseline: 1.2108x; 1.2108x over previous
#include <cuda_runtime.h>
#include <math_constants.h>
#include <cstdint>

// Problem constants
#define S_LEN   4096
#define D_MODEL 512
#define H_NUM   8
#define HD      64
#define LDQKV   1536      // 3*D_MODEL

// Q pre-scale: 1/sqrt(64) * log2(e)  (softmax runs in exp2 domain)
#define Q_PRESCALE 0.18033688011112042f

// Scratch (no cudaMalloc allowed)
__device__ float g_qkv[S_LEN * LDQKV];      // [4096,1536] Q|K|V (tf32, Q pre-scaled)
__device__ float g_attn[S_LEN * D_MODEL];   // [4096,512]  attention out (tf32-rounded)
__device__ float g_qr [S_LEN * D_MODEL];    // query, tf32-rounded
__device__ float g_wi [3 * D_MODEL * D_MODEL]; // in_proj_weight, tf32-rounded
__device__ float g_wo [D_MODEL * D_MODEL];  // out_proj_weight, tf32-rounded

// ---------------------------------------------------------------------------
// Helpers
// ---------------------------------------------------------------------------
__device__ __forceinline__ uint32_t f2tf32(float x) {
    uint32_t r;
    asm("cvt.rna.tf32.f32 %0, %1;" : "=r"(r) : "f"(x));
    return r;
}

__device__ __forceinline__ float ex2f(float x) {
    float y;
    asm("ex2.approx.ftz.f32 %0, %1;" : "=f"(y) : "f"(x));
    return y;
}

__device__ __forceinline__ void mma_tf32(float d[4], const uint32_t a[4],
                                         const uint32_t b[2], const float c[4]) {
    asm volatile(
        "mma.sync.aligned.m16n8k8.row.col.f32.tf32.tf32.f32 "
        "{%0,%1,%2,%3}, {%4,%5,%6,%7}, {%8,%9}, {%10,%11,%12,%13};"
        : "=f"(d[0]), "=f"(d[1]), "=f"(d[2]), "=f"(d[3])
        : "r"(a[0]), "r"(a[1]), "r"(a[2]), "r"(a[3]),
          "r"(b[0]), "r"(b[1]),
          "f"(c[0]), "f"(c[1]), "f"(c[2]), "f"(c[3]));
}

__device__ __forceinline__ uint32_t smem_u32(const void* p) {
    uint32_t a;
    asm("{ .reg .u64 t; cvta.to.shared.u64 t, %1; cvt.u32.u64 %0, t; }"
        : "=r"(a) : "l"(p));
    return a;
}

// cp.async.ca: 16B gmem->smem, L1-preserving (the .cg variant regressed in R4)
__device__ __forceinline__ void cp_async16(uint32_t dst, const void* src) {
    asm volatile("cp.async.ca.shared.global [%0], [%1], 16;"
                 :: "r"(dst), "l"(src));
}
#define CP_COMMIT()  asm volatile("cp.async.commit_group;")
#define CP_WAIT0()   asm volatile("cp.async.wait_group 0;")

// ---------------------------------------------------------------------------
// Elementwise tf32 rounding pass (src -> dst), float4 granular.
// ---------------------------------------------------------------------------
__global__ void round_tf32_kernel(const float* __restrict__ src,
                                  float* __restrict__ dst, int n4) {
    int i = blockIdx.x * blockDim.x + threadIdx.x;
    if (i < n4) {
        float4 v = *(const float4*)(src + 4 * i);
        v.x = __uint_as_float(f2tf32(v.x));
        v.y = __uint_as_float(f2tf32(v.y));
        v.z = __uint_as_float(f2tf32(v.z));
        v.w = __uint_as_float(f2tf32(v.w));
        *(float4*)(dst + 4 * i) = v;
    }
}

// ---------------------------------------------------------------------------
// tf32 tensor-core GEMM: C[M,N] = A[M,K] @ B[N,K]^T + bias[N]
// 128x128 CTA tile, 128 threads = 4 warps in a 2x2 grid of 64x64 warp tiles:
// 1.0 LDS per mma (vs 1.5 at 32x64) -> -33% smem crossbar traffic, the
// measured GEMM bottleneck (issue 24%, tensor 34%). 128 threads raises the
// min-blocks-2 register cap to 256 (acc 128 + frags fit, no spill).
// Inputs ALREADY tf32-valued; staging via cp.async.ca double buffer.
// qkv_round=1: epilogue scales Q columns (<512) by Q_PRESCALE + rounds all
// outputs to tf32 so the flash kernel stages with raw copies.
// ---------------------------------------------------------------------------
#define GLD 36
#define GEMM_SMEM (2 * 2 * 128 * GLD * 4)   // 73728 bytes

__global__ void __launch_bounds__(128, 2) gemm_tf32_bias(
    const float* __restrict__ A, const float* __restrict__ B,
    const float* __restrict__ bias, float* __restrict__ C,
    int M, int N, int K, int qkv_round)
{
    extern __shared__ float sm[];
    float* As[2] = { sm,                 sm + 128 * GLD     };
    float* Bs[2] = { sm + 2 * 128 * GLD, sm + 3 * 128 * GLD };

    const int tid  = threadIdx.x;
    const int lane = tid & 31;
    const int wid  = tid >> 5;          // 0..3
    const int qc   = lane & 3;
    const int qg   = lane >> 2;
    const int wm   = (wid & 1) * 64;    // 2x2 warp grid, 64x64 warp tiles
    const int wn   = (wid >> 1) * 64;
    const int m0   = blockIdx.y * 128;
    const int n0   = blockIdx.x * 128;

    // staging: 128 threads cover a 128x32 tile in 8 steps of 16 rows
    const int srow = tid >> 3;          // 0..15
    const int sc4  = (tid & 7) << 2;    // 0..28
    const uint32_t aS[2] = { smem_u32(As[0] + srow * GLD + sc4),
                             smem_u32(As[1] + srow * GLD + sc4) };
    const uint32_t bS[2] = { smem_u32(Bs[0] + srow * GLD + sc4),
                             smem_u32(Bs[1] + srow * GLD + sc4) };
    const uint32_t rstep = 16 * GLD * 4;   // bytes per 16-row step

    float acc[4][8][4];
#pragma unroll
    for (int mf = 0; mf < 4; mf++)
#pragma unroll
        for (int nf = 0; nf < 8; nf++)
#pragma unroll
            for (int j = 0; j < 4; j++) acc[mf][nf][j] = 0.0f;

    const int nt = K / 32;

    // prologue: stage tile 0
    {
        const float* ag = A + (size_t)(m0 + srow) * K + sc4;
        const float* bg = B + (size_t)(n0 + srow) * K + sc4;
#pragma unroll
        for (int i = 0; i < 8; i++) {
            cp_async16(aS[0] + i * rstep, ag + (size_t)(16 * i) * K);
            cp_async16(bS[0] + i * rstep, bg + (size_t)(16 * i) * K);
        }
    }
    CP_COMMIT();
    CP_WAIT0();
    __syncthreads();

    for (int t = 0; t < nt; t++) {
        const int cur = t & 1;
        if (t + 1 < nt) {
            const int nxt = cur ^ 1;
            int k0 = (t + 1) * 32;
            const float* ag = A + (size_t)(m0 + srow) * K + k0 + sc4;
            const float* bg = B + (size_t)(n0 + srow) * K + k0 + sc4;
#pragma unroll
            for (int i = 0; i < 8; i++) {
                cp_async16(aS[nxt] + i * rstep, ag + (size_t)(16 * i) * K);
                cp_async16(bS[nxt] + i * rstep, bg + (size_t)(16 * i) * K);
            }
            CP_COMMIT();
        }

        const float* as = As[cur];
        const float* bs = Bs[cur];
#pragma unroll
        for (int kc = 0; kc < 4; kc++) {
            uint32_t bfr[8][2];
#pragma unroll
            for (int nf = 0; nf < 8; nf++) {
                const float* bp = bs + (wn + nf * 8 + qg) * GLD + kc * 8 + qc;
                bfr[nf][0] = __float_as_uint(bp[0]);
                bfr[nf][1] = __float_as_uint(bp[4]);
            }
#pragma unroll
            for (int mf = 0; mf < 4; mf++) {
                const float* ap = as + (wm + mf * 16 + qg) * GLD + kc * 8 + qc;
                uint32_t afr[4];
                afr[0] = __float_as_uint(ap[0]);
                afr[1] = __float_as_uint(ap[8 * GLD]);
                afr[2] = __float_as_uint(ap[4]);
                afr[3] = __float_as_uint(ap[8 * GLD + 4]);
#pragma unroll
                for (int nf = 0; nf < 8; nf++)
                    mma_tf32(acc[mf][nf], afr, bfr[nf], acc[mf][nf]);
            }
        }

        CP_WAIT0();
        __syncthreads();
    }

#pragma unroll
    for (int mf = 0; mf < 4; mf++) {
        int row0 = m0 + wm + mf * 16 + qg;
#pragma unroll
        for (int nf = 0; nf < 8; nf++) {
            int col = n0 + wn + nf * 8 + 2 * qc;
            float b0 = bias[col], b1 = bias[col + 1];
            float2 v0 = make_float2(acc[mf][nf][0] + b0, acc[mf][nf][1] + b1);
            float2 v1 = make_float2(acc[mf][nf][2] + b0, acc[mf][nf][3] + b1);
            if (qkv_round) {
                float sc = (col < D_MODEL) ? Q_PRESCALE : 1.0f;  // scale Q only
                v0.x = __uint_as_float(f2tf32(v0.x * sc));
                v0.y = __uint_as_float(f2tf32(v0.y * sc));
                v1.x = __uint_as_float(f2tf32(v1.x * sc));
                v1.y = __uint_as_float(f2tf32(v1.y * sc));
            }
            *(float2*)(C + (size_t)row0 * N + col)       = v0;
            *(float2*)(C + (size_t)(row0 + 8) * N + col) = v1;
        }
    }
}

// ---------------------------------------------------------------------------
// Flash attention (R10 config VERBATIM -- best measured, 346.7us total).
// tf32 mma, Br=128 / Bc=64 / Hd=64, 4 warps, 32 q-rows/warp, single-buffer
// KV (70.6KB smem x2 CTAs leaves ~87KB L1 -> staging LDGs are L1 hits for
// the co-resident same-head CTA; every 106KB-smem variant regressed).
// kc-outer shared fragments, scalar LDS, exp2 softmax, two syncs per tile.
// Epilogue rounds attn to tf32 so the out-proj can cp.async raw.
// ---------------------------------------------------------------------------
#define LDA 68
#define LDB 72
#define FLASH_SMEM ((64 * LDA + 64 * LDB + 128 * LDA) * 4)   // 70656 B

__global__ void __launch_bounds__(128, 2) flash_mma_kernel(
    const float* __restrict__ qkv, float* __restrict__ attn_out)
{
    extern __shared__ float sm[];
    float* Ks = sm;                        // [64][LDA]
    float* Vs = sm + 64 * LDA;             // [64][LDB]
    float* Ps = sm + 64 * LDA + 64 * LDB;  // [128][LDA]  (Q staging, then P)

    const int tid  = threadIdx.x;
    const int lane = tid & 31;
    const int wid  = tid >> 5;
    const int qc   = lane & 3;
    const int qg   = lane >> 2;
    const int h    = blockIdx.y;
    const int q0   = blockIdx.x * 128;
    const int colb = h * HD;

    // ---- Stage Q tile (pre-scaled, pre-rounded): raw copy into Ps ----
#pragma unroll
    for (int i = 0; i < 16; i++) {
        int f   = tid + i * 128;
        int row = f >> 4;
        int c4  = (f & 15) << 2;
        *(float4*)(Ps + row * LDA + c4) =
            *(const float4*)(qkv + (size_t)(q0 + row) * LDQKV + colb + c4);
    }
    __syncthreads();

    // ---- Q fragments to registers: 2 m-frags x 8 k-chunks ----
    uint32_t qf[2][8][4];
#pragma unroll
    for (int mf = 0; mf < 2; mf++) {
        const int r0 = wid * 32 + mf * 16 + qg;
#pragma unroll
        for (int kc = 0; kc < 8; kc++) {
            int d0 = kc * 8;
            qf[mf][kc][0] = __float_as_uint(Ps[r0 * LDA + d0 + qc]);
            qf[mf][kc][1] = __float_as_uint(Ps[(r0 + 8) * LDA + d0 + qc]);
            qf[mf][kc][2] = __float_as_uint(Ps[r0 * LDA + d0 + qc + 4]);
            qf[mf][kc][3] = __float_as_uint(Ps[(r0 + 8) * LDA + d0 + qc + 4]);
        }
    }

    float o[2][8][4];
#pragma unroll
    for (int mf = 0; mf < 2; mf++)
#pragma unroll
        for (int nt = 0; nt < 8; nt++)
#pragma unroll
            for (int j = 0; j < 4; j++) o[mf][nt][j] = 0.0f;
    float m_run[2][2] = { {-CUDART_INF_F, -CUDART_INF_F},
                          {-CUDART_INF_F, -CUDART_INF_F} };
    float l_run[2][2] = { {0.f, 0.f}, {0.f, 0.f} };

    const int srow = tid >> 4;          // staging row 0..7 (stride 8)
    const int sc4  = (tid & 15) << 2;   // staging col 0..60

    for (int k0 = 0; k0 < S_LEN; k0 += 64) {
        __syncthreads();   // prev Ps/Ks/Vs reads done (covers Q-frag reads on t=0)
        // ---- Stage K, V tiles: raw LDG.128 -> STS.128 copy (L1-resident) ----
        {
            const float* kbase = qkv + (size_t)(k0 + srow) * LDQKV + colb + D_MODEL + sc4;
#pragma unroll
            for (int r = 0; r < 8; r++) {
                *(float4*)(Ks + (srow + r * 8) * LDA + sc4) =
                    *(const float4*)(kbase + (size_t)(r * 8) * LDQKV);
                *(float4*)(Vs + (srow + r * 8) * LDB + sc4) =
                    *(const float4*)(kbase + (size_t)(r * 8) * LDQKV + D_MODEL);
            }
        }
        __syncthreads();

        // ---- S = Q K^T, kc-outer: K B-frags loaded once, shared by both mf ----
        float s[2][8][4];
#pragma unroll
        for (int mf = 0; mf < 2; mf++)
#pragma unroll
            for (int nt = 0; nt < 8; nt++)
#pragma unroll
                for (int j = 0; j < 4; j++) s[mf][nt][j] = 0.0f;

#pragma unroll
        for (int kc = 0; kc < 8; kc++) {
            uint32_t bfr[8][2];
#pragma unroll
            for (int nt = 0; nt < 8; nt++) {
                const float* kb = Ks + (nt * 8 + qg) * LDA + kc * 8 + qc;
                bfr[nt][0] = __float_as_uint(kb[0]);
                bfr[nt][1] = __float_as_uint(kb[4]);
            }
#pragma unroll
            for (int mf = 0; mf < 2; mf++)
#pragma unroll
                for (int nt = 0; nt < 8; nt++)
                    mma_tf32(s[mf][nt], qf[mf][kc], bfr[nt], s[mf][nt]);
        }

        // ---- Online softmax per m-fragment (exp2 domain), store P ----
#pragma unroll
        for (int mf = 0; mf < 2; mf++) {
            const int r0 = wid * 32 + mf * 16 + qg;
            const int r1 = r0 + 8;

            float mlo = -CUDART_INF_F, mhi = -CUDART_INF_F;
#pragma unroll
            for (int nt = 0; nt < 8; nt++) {
                mlo = fmaxf(mlo, fmaxf(s[mf][nt][0], s[mf][nt][1]));
                mhi = fmaxf(mhi, fmaxf(s[mf][nt][2], s[mf][nt][3]));
            }
            mlo = fmaxf(mlo, __shfl_xor_sync(0xffffffffu, mlo, 1));
            mlo = fmaxf(mlo, __shfl_xor_sync(0xffffffffu, mlo, 2));
            mhi = fmaxf(mhi, __shfl_xor_sync(0xffffffffu, mhi, 1));
            mhi = fmaxf(mhi, __shfl_xor_sync(0xffffffffu, mhi, 2));

            float mnlo = fmaxf(m_run[mf][0], mlo);
            float mnhi = fmaxf(m_run[mf][1], mhi);
            float alo  = ex2f(m_run[mf][0] - mnlo);   // 0 on first tile
            float ahi  = ex2f(m_run[mf][1] - mnhi);
            m_run[mf][0] = mnlo; m_run[mf][1] = mnhi;

            float tlo = 0.0f, thi = 0.0f;
#pragma unroll
            for (int nt = 0; nt < 8; nt++) {
                float p0 = ex2f(s[mf][nt][0] - mnlo);
                float p1 = ex2f(s[mf][nt][1] - mnlo);
                float p2 = ex2f(s[mf][nt][2] - mnhi);
                float p3 = ex2f(s[mf][nt][3] - mnhi);
                tlo += p0 + p1;
                thi += p2 + p3;
                uint2 plo = make_uint2(f2tf32(p0), f2tf32(p1));
                uint2 phi = make_uint2(f2tf32(p2), f2tf32(p3));
                *(uint2*)(Ps + r0 * LDA + nt * 8 + 2 * qc) = plo;
                *(uint2*)(Ps + r1 * LDA + nt * 8 + 2 * qc) = phi;
            }
            tlo += __shfl_xor_sync(0xffffffffu, tlo, 1);
            tlo += __shfl_xor_sync(0xffffffffu, tlo, 2);
            thi += __shfl_xor_sync(0xffffffffu, thi, 1);
            thi += __shfl_xor_sync(0xffffffffu, thi, 2);
            l_run[mf][0] = l_run[mf][0] * alo + tlo;
            l_run[mf][1] = l_run[mf][1] * ahi + thi;

#pragma unroll
            for (int nt = 0; nt < 8; nt++) {
                o[mf][nt][0] *= alo; o[mf][nt][1] *= alo;
                o[mf][nt][2] *= ahi; o[mf][nt][3] *= ahi;
            }
        }

        __syncwarp();   // P rows are warp-private; order STS before LDS

        // ---- O += P V  (kc-outer: V B-frags shared by both m-frags) ----
#pragma unroll
        for (int kc = 0; kc < 8; kc++) {
            uint32_t vfr[8][2];
#pragma unroll
            for (int nt = 0; nt < 8; nt++) {
                vfr[nt][0] = __float_as_uint(Vs[(kc * 8 + qc) * LDB + nt * 8 + qg]);
                vfr[nt][1] = __float_as_uint(Vs[(kc * 8 + qc + 4) * LDB + nt * 8 + qg]);
            }
#pragma unroll
            for (int mf = 0; mf < 2; mf++) {
                const int r0 = wid * 32 + mf * 16 + qg;
                const int r1 = r0 + 8;
                uint32_t a[4];
                a[0] = __float_as_uint(Ps[r0 * LDA + kc * 8 + qc]);
                a[1] = __float_as_uint(Ps[r1 * LDA + kc * 8 + qc]);
                a[2] = __float_as_uint(Ps[r0 * LDA + kc * 8 + qc + 4]);
                a[3] = __float_as_uint(Ps[r1 * LDA + kc * 8 + qc + 4]);
#pragma unroll
                for (int nt = 0; nt < 8; nt++)
                    mma_tf32(o[mf][nt], a, vfr[nt], o[mf][nt]);
            }
        }
    }

    // ---- Epilogue: normalize + round to tf32 (out-proj stages raw) ----
#pragma unroll
    for (int mf = 0; mf < 2; mf++) {
        const int r0 = wid * 32 + mf * 16 + qg;
        const int r1 = r0 + 8;
        float ilo = 1.0f / l_run[mf][0];
        float ihi = 1.0f / l_run[mf][1];
#pragma unroll
        for (int nt = 0; nt < 8; nt++) {
            uint2 vlo = make_uint2(f2tf32(o[mf][nt][0] * ilo), f2tf32(o[mf][nt][1] * ilo));
            uint2 vhi = make_uint2(f2tf32(o[mf][nt][2] * ihi), f2tf32(o[mf][nt][3] * ihi));
            *(uint2*)(attn_out + (size_t)(q0 + r0) * D_MODEL + colb + nt * 8 + 2 * qc) = vlo;
            *(uint2*)(attn_out + (size_t)(q0 + r1) * D_MODEL + colb + nt * 8 + 2 * qc) = vhi;
        }
    }
}

// ---------------------------------------------------------------------------
// Launch: pre-round -> QKV proj -> flash -> out proj
// ---------------------------------------------------------------------------
extern "C" void kernel_launch(void* const* d_in, const int* in_sizes, int n_in,
                              void* d_out, int out_size)
{
    const float* query = (const float*)d_in[0];   // [1,4096,512]
    const float* w_in  = (const float*)d_in[1];   // [1536,512]
    const float* b_in  = (const float*)d_in[2];   // [1536]
    const float* w_out = (const float*)d_in[3];   // [512,512]
    const float* b_out = (const float*)d_in[4];   // [512]
    float*       out   = (float*)d_out;           // [1,4096,512]

    float *qkv, *attn, *qr, *wi, *wo;
    cudaGetSymbolAddress((void**)&qkv,  g_qkv);
    cudaGetSymbolAddress((void**)&attn, g_attn);
    cudaGetSymbolAddress((void**)&qr,   g_qr);
    cudaGetSymbolAddress((void**)&wi,   g_wi);
    cudaGetSymbolAddress((void**)&wo,   g_wo);

    cudaFuncSetAttribute(gemm_tf32_bias,
                         cudaFuncAttributeMaxDynamicSharedMemorySize, GEMM_SMEM);
    cudaFuncSetAttribute(flash_mma_kernel,
                         cudaFuncAttributeMaxDynamicSharedMemorySize, FLASH_SMEM);

    // 0) Pre-round inputs to tf32 (idempotent rounding copies)
    {
        int nq = S_LEN * D_MODEL / 4;          // 524288
        int ni = 3 * D_MODEL * D_MODEL / 4;    // 196608
        int no = D_MODEL * D_MODEL / 4;        // 65536
        round_tf32_kernel<<<(nq + 255) / 256, 256>>>(query, qr, nq);
        round_tf32_kernel<<<(ni + 255) / 256, 256>>>(w_in,  wi, ni);
        round_tf32_kernel<<<(no + 255) / 256, 256>>>(w_out, wo, no);
    }

    // 1) QKV projection (+ Q pre-scale incl. log2e + tf32 rounding)
    {
        dim3 grid(LDQKV / 128, S_LEN / 128);   // (12, 32)
        gemm_tf32_bias<<<grid, 128, GEMM_SMEM>>>(qr, wi, b_in, qkv,
                                                 S_LEN, LDQKV, D_MODEL, 1);
    }

    // 2) Flash attention per head (R10 config, frozen)
    {
        dim3 grid(S_LEN / 128, H_NUM);   // (32, 8) = 256 CTAs
        flash_mma_kernel<<<grid, 128, FLASH_SMEM>>>(qkv, attn);
    }

    // 3) Output projection (full fp32 output)
    {
        dim3 grid(D_MODEL / 128, S_LEN / 128);  // (4, 32)
        gemm_tf32_bias<<<grid, 128, GEMM_SMEM>>>(attn, wo, b_out, out,
                                                 S_LEN, D_MODEL, D_MODEL, 0);
    }
}

// round 15
// speedup vs baseline: 1.8528x; 1.5302x over previous
#include <cuda_runtime.h>
#include <cuda_fp16.h>
#include <math_constants.h>
#include <cstdint>

// Problem constants
#define S_LEN   4096
#define D_MODEL 512
#define H_NUM   8
#define HD      64
#define LDQKV   1536      // 3*D_MODEL

// Q pre-scale: 1/sqrt(64) * log2(e)  (softmax runs in exp2 domain)
#define Q_PRESCALE 0.18033688011112042f

// Scratch (no cudaMalloc allowed) -- all fp16 now
__device__ __half g_qkv[S_LEN * LDQKV];       // [4096,1536] Q|K|V (fp16, Q pre-scaled)
__device__ __half g_attn[S_LEN * D_MODEL];    // [4096,512]  attention out (fp16)
__device__ __half g_qr [S_LEN * D_MODEL];     // query, fp16
__device__ __half g_wi [3 * D_MODEL * D_MODEL]; // in_proj_weight, fp16
__device__ __half g_wo [D_MODEL * D_MODEL];   // out_proj_weight, fp16

// ---------------------------------------------------------------------------
// Helpers
// ---------------------------------------------------------------------------
__device__ __forceinline__ float ex2f(float x) {
    float y;
    asm("ex2.approx.ftz.f32 %0, %1;" : "=f"(y) : "f"(x));
    return y;
}

// m16n8k16 fp16 mma, fp32 accumulate
__device__ __forceinline__ void mma_f16(float d[4], const uint32_t a[4],
                                        const uint32_t b[2], const float c[4]) {
    asm volatile(
        "mma.sync.aligned.m16n8k16.row.col.f32.f16.f16.f32 "
        "{%0,%1,%2,%3}, {%4,%5,%6,%7}, {%8,%9}, {%10,%11,%12,%13};"
        : "=f"(d[0]), "=f"(d[1]), "=f"(d[2]), "=f"(d[3])
        : "r"(a[0]), "r"(a[1]), "r"(a[2]), "r"(a[3]),
          "r"(b[0]), "r"(b[1]),
          "f"(c[0]), "f"(c[1]), "f"(c[2]), "f"(c[3]));
}

__device__ __forceinline__ uint32_t smem_u32(const void* p) {
    uint32_t a;
    asm("{ .reg .u64 t; cvta.to.shared.u64 t, %1; cvt.u32.u64 %0, t; }"
        : "=r"(a) : "l"(p));
    return a;
}

// cp.async.ca: 16B gmem->smem, L1-preserving
__device__ __forceinline__ void cp_async16(uint32_t dst, const void* src) {
    asm volatile("cp.async.ca.shared.global [%0], [%1], 16;"
                 :: "r"(dst), "l"(src));
}
#define CP_COMMIT()  asm volatile("cp.async.commit_group;")
#define CP_WAIT0()   asm volatile("cp.async.wait_group 0;")

// ---------------------------------------------------------------------------
// Elementwise fp32 -> fp16 rounding pass (src -> dst), 4 elems/thread.
// ---------------------------------------------------------------------------
__global__ void round_f16_kernel(const float* __restrict__ src,
                                 __half* __restrict__ dst, int n4) {
    int i = blockIdx.x * blockDim.x + threadIdx.x;
    if (i < n4) {
        float4 v = *(const float4*)(src + 4 * i);
        __half2 h01 = __floats2half2_rn(v.x, v.y);
        __half2 h23 = __floats2half2_rn(v.z, v.w);
        *(__half2*)(dst + 4 * i)     = h01;
        *(__half2*)(dst + 4 * i + 2) = h23;
    }
}

// ---------------------------------------------------------------------------
// fp16 tensor-core GEMM (m16n8k16): C[M,N] = A[M,K] @ B[N,K]^T + bias[N]
// 128x128 CTA tile, 128 threads = 2x2 warp grid of 64x64 warp tiles (R13
// winner structure). A,B fp16; accumulate fp32. cp.async.ca double buffer.
// qkv_round=1: epilogue scales Q columns (<512) by Q_PRESCALE and stores
// fp16 to C (half*); else stores fp32 (float*).
// Smem pad LDH=40 halves: fragment-load bank = 20*qg + qc (+offs) mod 32 ->
// all 32 lanes distinct (gcd(20,32)=4, 20/4 odd).
// ---------------------------------------------------------------------------
#define LDH 40
#define GEMM_SMEM (2 * 2 * 128 * LDH * 2)   // 40960 bytes

__global__ void __launch_bounds__(128, 2) gemm_f16_bias(
    const __half* __restrict__ A, const __half* __restrict__ B,
    const float* __restrict__ bias, void* __restrict__ Cv,
    int M, int N, int K, int qkv_round)
{
    extern __shared__ __half smh[];
    __half* As[2] = { smh,                 smh + 128 * LDH     };
    __half* Bs[2] = { smh + 2 * 128 * LDH, smh + 3 * 128 * LDH };

    const int tid  = threadIdx.x;
    const int lane = tid & 31;
    const int wid  = tid >> 5;          // 0..3
    const int qc   = lane & 3;
    const int qg   = lane >> 2;
    const int wm   = (wid & 1) * 64;    // 2x2 warp grid, 64x64 warp tiles
    const int wn   = (wid >> 1) * 64;
    const int m0   = blockIdx.y * 128;
    const int n0   = blockIdx.x * 128;

    // staging: tile = 128 rows x 32 halves (64B = 4 x 16B chunks per row)
    // 512 chunks / 128 threads = 4 per thread: id = tid + i*128
    uint32_t aS[2][4], bS[2][4];
#pragma unroll
    for (int i = 0; i < 4; i++) {
        int id  = tid + i * 128;
        int row = id >> 2;
        int c8  = (id & 3) * 8;         // halves offset
        aS[0][i] = smem_u32(As[0] + row * LDH + c8);
        aS[1][i] = smem_u32(As[1] + row * LDH + c8);
        bS[0][i] = smem_u32(Bs[0] + row * LDH + c8);
        bS[1][i] = smem_u32(Bs[1] + row * LDH + c8);
    }

    float acc[4][8][4];
#pragma unroll
    for (int mf = 0; mf < 4; mf++)
#pragma unroll
        for (int nf = 0; nf < 8; nf++)
#pragma unroll
            for (int j = 0; j < 4; j++) acc[mf][nf][j] = 0.0f;

    const int nt = K / 32;

    // prologue: stage tile 0
#pragma unroll
    for (int i = 0; i < 4; i++) {
        int id  = tid + i * 128;
        int row = id >> 2;
        int c8  = (id & 3) * 8;
        cp_async16(aS[0][i], A + (size_t)(m0 + row) * K + c8);
        cp_async16(bS[0][i], B + (size_t)(n0 + row) * K + c8);
    }
    CP_COMMIT();
    CP_WAIT0();
    __syncthreads();

    for (int t = 0; t < nt; t++) {
        const int cur = t & 1;
        if (t + 1 < nt) {
            const int nxt = cur ^ 1;
            int k0 = (t + 1) * 32;
#pragma unroll
            for (int i = 0; i < 4; i++) {
                int id  = tid + i * 128;
                int row = id >> 2;
                int c8  = (id & 3) * 8;
                cp_async16(aS[nxt][i], A + (size_t)(m0 + row) * K + k0 + c8);
                cp_async16(bS[nxt][i], B + (size_t)(n0 + row) * K + k0 + c8);
            }
            CP_COMMIT();
        }

        const __half* as = As[cur];
        const __half* bs = Bs[cur];
#pragma unroll
        for (int kc = 0; kc < 2; kc++) {    // 2 x k16 chunks per K=32 tile
            uint32_t bfr[8][2];
#pragma unroll
            for (int nf = 0; nf < 8; nf++) {
                const __half* bp = bs + (wn + nf * 8 + qg) * LDH + kc * 16 + 2 * qc;
                bfr[nf][0] = *(const uint32_t*)(bp);
                bfr[nf][1] = *(const uint32_t*)(bp + 8);
            }
#pragma unroll
            for (int mf = 0; mf < 4; mf++) {
                const __half* ap = as + (wm + mf * 16 + qg) * LDH + kc * 16 + 2 * qc;
                uint32_t afr[4];
                afr[0] = *(const uint32_t*)(ap);
                afr[1] = *(const uint32_t*)(ap + 8 * LDH);
                afr[2] = *(const uint32_t*)(ap + 8);
                afr[3] = *(const uint32_t*)(ap + 8 * LDH + 8);
#pragma unroll
                for (int nf = 0; nf < 8; nf++)
                    mma_f16(acc[mf][nf], afr, bfr[nf], acc[mf][nf]);
            }
        }

        CP_WAIT0();
        __syncthreads();
    }

    // epilogue
#pragma unroll
    for (int mf = 0; mf < 4; mf++) {
        int row0 = m0 + wm + mf * 16 + qg;
#pragma unroll
        for (int nf = 0; nf < 8; nf++) {
            int col = n0 + wn + nf * 8 + 2 * qc;
            float b0 = bias[col], b1 = bias[col + 1];
            float v00 = acc[mf][nf][0] + b0, v01 = acc[mf][nf][1] + b1;
            float v10 = acc[mf][nf][2] + b0, v11 = acc[mf][nf][3] + b1;
            if (qkv_round) {
                float sc = (col < D_MODEL) ? Q_PRESCALE : 1.0f;  // scale Q only
                __half* C = (__half*)Cv;
                *(__half2*)(C + (size_t)row0 * N + col) =
                    __floats2half2_rn(v00 * sc, v01 * sc);
                *(__half2*)(C + (size_t)(row0 + 8) * N + col) =
                    __floats2half2_rn(v10 * sc, v11 * sc);
            } else {
                float* C = (float*)Cv;
                *(float2*)(C + (size_t)row0 * N + col)       = make_float2(v00, v01);
                *(float2*)(C + (size_t)(row0 + 8) * N + col) = make_float2(v10, v11);
            }
        }
    }
}

// ---------------------------------------------------------------------------
// Flash attention, fp16 mma (m16n8k16), Br=128 / Bc=64 / Hd=64, 4 warps,
// 32 q-rows/warp -- R10/R13 winning structure, dtype-ported to fp16:
// same kc-outer shared fragments, same two syncs per tile, exp2 softmax.
// Smem now 36.9KB/CTA (x2 CTAs -> ~150KB L1 left; staging LDGs stay L1-hot).
// V B-frags need column pairs: two u16 LDS + pack (conservative, no new
// ldmatrix mappings). Pad LDH_F=72 halves (36 words === 4 mod 32): 32-bit
// fragment-load bank = 4*qg + qc (+8k) mod 32 -> conflict-free.
// ---------------------------------------------------------------------------
#define LDH_F 72
#define FLASH_SMEM ((64 * LDH_F + 64 * LDH_F + 128 * LDH_F) * 2)   // 36864 B

__global__ void __launch_bounds__(128, 2) flash_mma_kernel(
    const __half* __restrict__ qkv, __half* __restrict__ attn_out)
{
    extern __shared__ __half smh[];
    __half* Ks = smh;                            // [64][LDH_F]
    __half* Vs = smh + 64 * LDH_F;               // [64][LDH_F]
    __half* Ps = smh + 2 * 64 * LDH_F;           // [128][LDH_F] (Q staging, then P)

    const int tid  = threadIdx.x;
    const int lane = tid & 31;
    const int wid  = tid >> 5;
    const int qc   = lane & 3;
    const int qg   = lane >> 2;
    const int h    = blockIdx.y;
    const int q0   = blockIdx.x * 128;
    const int colb = h * HD;

    // ---- Stage Q tile (pre-scaled, fp16): raw 16B copies into Ps ----
    // 128 rows x 64 halves = 1024 16B-chunks; 128 threads x 8 iters
#pragma unroll
    for (int i = 0; i < 8; i++) {
        int id  = tid + i * 128;
        int row = id >> 3;
        int c8  = (id & 7) * 8;
        *(uint4*)(Ps + row * LDH_F + c8) =
            *(const uint4*)(qkv + (size_t)(q0 + row) * LDQKV + colb + c8);
    }
    __syncthreads();

    // ---- Q fragments to registers: 2 m-frags x 4 k16-chunks ----
    uint32_t qf[2][4][4];
#pragma unroll
    for (int mf = 0; mf < 2; mf++) {
        const int r0 = wid * 32 + mf * 16 + qg;
#pragma unroll
        for (int kc = 0; kc < 4; kc++) {
            const __half* qp = Ps + r0 * LDH_F + kc * 16 + 2 * qc;
            qf[mf][kc][0] = *(const uint32_t*)(qp);
            qf[mf][kc][1] = *(const uint32_t*)(qp + 8 * LDH_F);
            qf[mf][kc][2] = *(const uint32_t*)(qp + 8);
            qf[mf][kc][3] = *(const uint32_t*)(qp + 8 * LDH_F + 8);
        }
    }

    float o[2][8][4];
#pragma unroll
    for (int mf = 0; mf < 2; mf++)
#pragma unroll
        for (int nt = 0; nt < 8; nt++)
#pragma unroll
            for (int j = 0; j < 4; j++) o[mf][nt][j] = 0.0f;
    float m_run[2][2] = { {-CUDART_INF_F, -CUDART_INF_F},
                          {-CUDART_INF_F, -CUDART_INF_F} };
    float l_run[2][2] = { {0.f, 0.f}, {0.f, 0.f} };

    // staging: 64 rows x 64 halves = 512 chunks; 128 threads x 4 iters
    const int srow = tid >> 3;          // 0..15
    const int sc8  = (tid & 7) * 8;     // halves 0..56

    for (int k0 = 0; k0 < S_LEN; k0 += 64) {
        __syncthreads();   // prev tile reads done (covers Q-frag reads on t=0)
        // ---- Stage K, V tiles: raw LDG.128 -> STS.128 (L1-resident) ----
        {
            const __half* kb = qkv + (size_t)(k0 + srow) * LDQKV + colb + D_MODEL + sc8;
#pragma unroll
            for (int r = 0; r < 4; r++) {
                *(uint4*)(Ks + (srow + r * 16) * LDH_F + sc8) =
                    *(const uint4*)(kb + (size_t)(r * 16) * LDQKV);
                *(uint4*)(Vs + (srow + r * 16) * LDH_F + sc8) =
                    *(const uint4*)(kb + (size_t)(r * 16) * LDQKV + D_MODEL);
            }
        }
        __syncthreads();

        // ---- S = Q K^T, kc-outer: K B-frags loaded once, shared by both mf ----
        float s[2][8][4];
#pragma unroll
        for (int mf = 0; mf < 2; mf++)
#pragma unroll
            for (int nt = 0; nt < 8; nt++)
#pragma unroll
                for (int j = 0; j < 4; j++) s[mf][nt][j] = 0.0f;

#pragma unroll
        for (int kc = 0; kc < 4; kc++) {
            uint32_t bfr[8][2];
#pragma unroll
            for (int nt = 0; nt < 8; nt++) {
                const __half* kp = Ks + (nt * 8 + qg) * LDH_F + kc * 16 + 2 * qc;
                bfr[nt][0] = *(const uint32_t*)(kp);
                bfr[nt][1] = *(const uint32_t*)(kp + 8);
            }
#pragma unroll
            for (int mf = 0; mf < 2; mf++)
#pragma unroll
                for (int nt = 0; nt < 8; nt++)
                    mma_f16(s[mf][nt], qf[mf][kc], bfr[nt], s[mf][nt]);
        }

        // ---- Online softmax per m-fragment (exp2 domain), store P (fp16) ----
#pragma unroll
        for (int mf = 0; mf < 2; mf++) {
            const int r0 = wid * 32 + mf * 16 + qg;
            const int r1 = r0 + 8;

            float mlo = -CUDART_INF_F, mhi = -CUDART_INF_F;
#pragma unroll
            for (int nt = 0; nt < 8; nt++) {
                mlo = fmaxf(mlo, fmaxf(s[mf][nt][0], s[mf][nt][1]));
                mhi = fmaxf(mhi, fmaxf(s[mf][nt][2], s[mf][nt][3]));
            }
            mlo = fmaxf(mlo, __shfl_xor_sync(0xffffffffu, mlo, 1));
            mlo = fmaxf(mlo, __shfl_xor_sync(0xffffffffu, mlo, 2));
            mhi = fmaxf(mhi, __shfl_xor_sync(0xffffffffu, mhi, 1));
            mhi = fmaxf(mhi, __shfl_xor_sync(0xffffffffu, mhi, 2));

            float mnlo = fmaxf(m_run[mf][0], mlo);
            float mnhi = fmaxf(m_run[mf][1], mhi);
            float alo  = ex2f(m_run[mf][0] - mnlo);   // 0 on first tile
            float ahi  = ex2f(m_run[mf][1] - mnhi);
            m_run[mf][0] = mnlo; m_run[mf][1] = mnhi;

            float tlo = 0.0f, thi = 0.0f;
#pragma unroll
            for (int nt = 0; nt < 8; nt++) {
                float p0 = ex2f(s[mf][nt][0] - mnlo);
                float p1 = ex2f(s[mf][nt][1] - mnlo);
                float p2 = ex2f(s[mf][nt][2] - mnhi);
                float p3 = ex2f(s[mf][nt][3] - mnhi);
                tlo += p0 + p1;
                thi += p2 + p3;
                *(__half2*)(Ps + r0 * LDH_F + nt * 8 + 2 * qc) = __floats2half2_rn(p0, p1);
                *(__half2*)(Ps + r1 * LDH_F + nt * 8 + 2 * qc) = __floats2half2_rn(p2, p3);
            }
            tlo += __shfl_xor_sync(0xffffffffu, tlo, 1);
            tlo += __shfl_xor_sync(0xffffffffu, tlo, 2);
            thi += __shfl_xor_sync(0xffffffffu, thi, 1);
            thi += __shfl_xor_sync(0xffffffffu, thi, 2);
            l_run[mf][0] = l_run[mf][0] * alo + tlo;
            l_run[mf][1] = l_run[mf][1] * ahi + thi;

#pragma unroll
            for (int nt = 0; nt < 8; nt++) {
                o[mf][nt][0] *= alo; o[mf][nt][1] *= alo;
                o[mf][nt][2] *= ahi; o[mf][nt][3] *= ahi;
            }
        }

        __syncwarp();   // P rows are warp-private; order STS before LDS

        // ---- O += P V  (kc-outer; V B-frags = 2x u16 + pack, shared) ----
#pragma unroll
        for (int kc = 0; kc < 4; kc++) {
            uint32_t vfr[8][2];
#pragma unroll
            for (int nt = 0; nt < 8; nt++) {
                const __half* vb = Vs + (kc * 16 + 2 * qc) * LDH_F + nt * 8 + qg;
                uint32_t x0 = *(const uint16_t*)(vb);
                uint32_t x1 = *(const uint16_t*)(vb + LDH_F);
                uint32_t x2 = *(const uint16_t*)(vb + 8 * LDH_F);
                uint32_t x3 = *(const uint16_t*)(vb + 9 * LDH_F);
                vfr[nt][0] = x0 | (x1 << 16);
                vfr[nt][1] = x2 | (x3 << 16);
            }
#pragma unroll
            for (int mf = 0; mf < 2; mf++) {
                const int r0 = wid * 32 + mf * 16 + qg;
                const __half* pp = Ps + r0 * LDH_F + kc * 16 + 2 * qc;
                uint32_t a[4];
                a[0] = *(const uint32_t*)(pp);
                a[1] = *(const uint32_t*)(pp + 8 * LDH_F);
                a[2] = *(const uint32_t*)(pp + 8);
                a[3] = *(const uint32_t*)(pp + 8 * LDH_F + 8);
#pragma unroll
                for (int nt = 0; nt < 8; nt++)
                    mma_f16(o[mf][nt], a, vfr[nt], o[mf][nt]);
            }
        }
    }

    // ---- Epilogue: normalize, store fp16 attn ----
#pragma unroll
    for (int mf = 0; mf < 2; mf++) {
        const int r0 = wid * 32 + mf * 16 + qg;
        const int r1 = r0 + 8;
        float ilo = 1.0f / l_run[mf][0];
        float ihi = 1.0f / l_run[mf][1];
#pragma unroll
        for (int nt = 0; nt < 8; nt++) {
            *(__half2*)(attn_out + (size_t)(q0 + r0) * D_MODEL + colb + nt * 8 + 2 * qc) =
                __floats2half2_rn(o[mf][nt][0] * ilo, o[mf][nt][1] * ilo);
            *(__half2*)(attn_out + (size_t)(q0 + r1) * D_MODEL + colb + nt * 8 + 2 * qc) =
                __floats2half2_rn(o[mf][nt][2] * ihi, o[mf][nt][3] * ihi);
        }
    }
}

// ---------------------------------------------------------------------------
// Launch: round-to-fp16 -> QKV proj -> flash -> out proj
// ---------------------------------------------------------------------------
extern "C" void kernel_launch(void* const* d_in, const int* in_sizes, int n_in,
                              void* d_out, int out_size)
{
    const float* query = (const float*)d_in[0];   // [1,4096,512]
    const float* w_in  = (const float*)d_in[1];   // [1536,512]
    const float* b_in  = (const float*)d_in[2];   // [1536]
    const float* w_out = (const float*)d_in[3];   // [512,512]
    const float* b_out = (const float*)d_in[4];   // [512]
    float*       out   = (float*)d_out;           // [1,4096,512]

    __half *qkv, *attn, *qr, *wi, *wo;
    cudaGetSymbolAddress((void**)&qkv,  g_qkv);
    cudaGetSymbolAddress((void**)&attn, g_attn);
    cudaGetSymbolAddress((void**)&qr,   g_qr);
    cudaGetSymbolAddress((void**)&wi,   g_wi);
    cudaGetSymbolAddress((void**)&wo,   g_wo);

    cudaFuncSetAttribute(gemm_f16_bias,
                         cudaFuncAttributeMaxDynamicSharedMemorySize, GEMM_SMEM);
    cudaFuncSetAttribute(flash_mma_kernel,
                         cudaFuncAttributeMaxDynamicSharedMemorySize, FLASH_SMEM);

    // 0) Round inputs to fp16
    {
        int nq = S_LEN * D_MODEL / 4;          // 524288
        int ni = 3 * D_MODEL * D_MODEL / 4;    // 196608
        int no = D_MODEL * D_MODEL / 4;        // 65536
        round_f16_kernel<<<(nq + 255) / 256, 256>>>(query, qr, nq);
        round_f16_kernel<<<(ni + 255) / 256, 256>>>(w_in,  wi, ni);
        round_f16_kernel<<<(no + 255) / 256, 256>>>(w_out, wo, no);
    }

    // 1) QKV projection (+ Q pre-scale incl. log2e; fp16 output)
    {
        dim3 grid(LDQKV / 128, S_LEN / 128);   // (12, 32)
        gemm_f16_bias<<<grid, 128, GEMM_SMEM>>>(qr, wi, b_in, qkv,
                                                S_LEN, LDQKV, D_MODEL, 1);
    }

    // 2) Flash attention per head (fp16 m16n8k16)
    {
        dim3 grid(S_LEN / 128, H_NUM);   // (32, 8) = 256 CTAs
        flash_mma_kernel<<<grid, 128, FLASH_SMEM>>>(qkv, attn);
    }

    // 3) Output projection (fp32 output)
    {
        dim3 grid(D_MODEL / 128, S_LEN / 128);  // (4, 32)
        gemm_f16_bias<<<grid, 128, GEMM_SMEM>>>(attn, wo, b_out, out,
                                                S_LEN, D_MODEL, D_MODEL, 0);
    }
}

// round 16
// speedup vs baseline: 1.9964x; 1.0775x over previous
#include <cuda_runtime.h>
#include <cuda_fp16.h>
#include <math_constants.h>
#include <cstdint>

// Problem constants
#define S_LEN   4096
#define D_MODEL 512
#define H_NUM   8
#define HD      64
#define LDQKV   1536      // 3*D_MODEL

// Q pre-scale: 1/sqrt(64) * log2(e)  (softmax runs in exp2 domain)
#define Q_PRESCALE 0.18033688011112042f

// Scratch (no cudaMalloc allowed) -- all fp16
__device__ __half g_qkv[S_LEN * LDQKV];       // [4096,1536] Q|K|V (fp16, Q pre-scaled)
__device__ __half g_attn[S_LEN * D_MODEL];    // [4096,512]  attention out (fp16)
__device__ __half g_qr [S_LEN * D_MODEL];     // query, fp16
__device__ __half g_wi [3 * D_MODEL * D_MODEL]; // in_proj_weight, fp16
__device__ __half g_wo [D_MODEL * D_MODEL];   // out_proj_weight, fp16

// ---------------------------------------------------------------------------
// Helpers
// ---------------------------------------------------------------------------
__device__ __forceinline__ float ex2f(float x) {
    float y;
    asm("ex2.approx.ftz.f32 %0, %1;" : "=f"(y) : "f"(x));
    return y;
}

// m16n8k16 fp16 mma, fp32 accumulate
__device__ __forceinline__ void mma_f16(float d[4], const uint32_t a[4],
                                        const uint32_t b[2], const float c[4]) {
    asm volatile(
        "mma.sync.aligned.m16n8k16.row.col.f32.f16.f16.f32 "
        "{%0,%1,%2,%3}, {%4,%5,%6,%7}, {%8,%9}, {%10,%11,%12,%13};"
        : "=f"(d[0]), "=f"(d[1]), "=f"(d[2]), "=f"(d[3])
        : "r"(a[0]), "r"(a[1]), "r"(a[2]), "r"(a[3]),
          "r"(b[0]), "r"(b[1]),
          "f"(c[0]), "f"(c[1]), "f"(c[2]), "f"(c[3]));
}

// ldmatrix x4 with per-matrix transpose (b16): canonical B-fragment loader
// for row-major K-major operands.
__device__ __forceinline__ void ldsm_x4_t(uint32_t& r0, uint32_t& r1,
                                          uint32_t& r2, uint32_t& r3, uint32_t addr) {
    asm volatile("ldmatrix.sync.aligned.m8n8.x4.trans.shared.b16 {%0,%1,%2,%3}, [%4];"
                 : "=r"(r0), "=r"(r1), "=r"(r2), "=r"(r3) : "r"(addr));
}

__device__ __forceinline__ uint32_t smem_u32(const void* p) {
    uint32_t a;
    asm("{ .reg .u64 t; cvta.to.shared.u64 t, %1; cvt.u32.u64 %0, t; }"
        : "=r"(a) : "l"(p));
    return a;
}

// cp.async.ca: 16B gmem->smem, L1-preserving
__device__ __forceinline__ void cp_async16(uint32_t dst, const void* src) {
    asm volatile("cp.async.ca.shared.global [%0], [%1], 16;"
                 :: "r"(dst), "l"(src));
}
#define CP_COMMIT()  asm volatile("cp.async.commit_group;")
#define CP_WAIT0()   asm volatile("cp.async.wait_group 0;")

// ---------------------------------------------------------------------------
// Elementwise fp32 -> fp16 rounding pass (src -> dst), 4 elems/thread.
// ---------------------------------------------------------------------------
__global__ void round_f16_kernel(const float* __restrict__ src,
                                 __half* __restrict__ dst, int n4) {
    int i = blockIdx.x * blockDim.x + threadIdx.x;
    if (i < n4) {
        float4 v = *(const float4*)(src + 4 * i);
        __half2 h01 = __floats2half2_rn(v.x, v.y);
        __half2 h23 = __floats2half2_rn(v.z, v.w);
        *(__half2*)(dst + 4 * i)     = h01;
        *(__half2*)(dst + 4 * i + 2) = h23;
    }
}

// ---------------------------------------------------------------------------
// fp16 tensor-core GEMM (m16n8k16): C[M,N] = A[M,K] @ B[N,K]^T + bias[N]
// (R14 winner, unchanged.)
// ---------------------------------------------------------------------------
#define LDH 40
#define GEMM_SMEM (2 * 2 * 128 * LDH * 2)   // 40960 bytes

__global__ void __launch_bounds__(128, 2) gemm_f16_bias(
    const __half* __restrict__ A, const __half* __restrict__ B,
    const float* __restrict__ bias, void* __restrict__ Cv,
    int M, int N, int K, int qkv_round)
{
    extern __shared__ __half smh[];
    __half* As[2] = { smh,                 smh + 128 * LDH     };
    __half* Bs[2] = { smh + 2 * 128 * LDH, smh + 3 * 128 * LDH };

    const int tid  = threadIdx.x;
    const int lane = tid & 31;
    const int wid  = tid >> 5;          // 0..3
    const int qc   = lane & 3;
    const int qg   = lane >> 2;
    const int wm   = (wid & 1) * 64;    // 2x2 warp grid, 64x64 warp tiles
    const int wn   = (wid >> 1) * 64;
    const int m0   = blockIdx.y * 128;
    const int n0   = blockIdx.x * 128;

    uint32_t aS[2][4], bS[2][4];
#pragma unroll
    for (int i = 0; i < 4; i++) {
        int id  = tid + i * 128;
        int row = id >> 2;
        int c8  = (id & 3) * 8;
        aS[0][i] = smem_u32(As[0] + row * LDH + c8);
        aS[1][i] = smem_u32(As[1] + row * LDH + c8);
        bS[0][i] = smem_u32(Bs[0] + row * LDH + c8);
        bS[1][i] = smem_u32(Bs[1] + row * LDH + c8);
    }

    float acc[4][8][4];
#pragma unroll
    for (int mf = 0; mf < 4; mf++)
#pragma unroll
        for (int nf = 0; nf < 8; nf++)
#pragma unroll
            for (int j = 0; j < 4; j++) acc[mf][nf][j] = 0.0f;

    const int nt = K / 32;

#pragma unroll
    for (int i = 0; i < 4; i++) {
        int id  = tid + i * 128;
        int row = id >> 2;
        int c8  = (id & 3) * 8;
        cp_async16(aS[0][i], A + (size_t)(m0 + row) * K + c8);
        cp_async16(bS[0][i], B + (size_t)(n0 + row) * K + c8);
    }
    CP_COMMIT();
    CP_WAIT0();
    __syncthreads();

    for (int t = 0; t < nt; t++) {
        const int cur = t & 1;
        if (t + 1 < nt) {
            const int nxt = cur ^ 1;
            int k0 = (t + 1) * 32;
#pragma unroll
            for (int i = 0; i < 4; i++) {
                int id  = tid + i * 128;
                int row = id >> 2;
                int c8  = (id & 3) * 8;
                cp_async16(aS[nxt][i], A + (size_t)(m0 + row) * K + k0 + c8);
                cp_async16(bS[nxt][i], B + (size_t)(n0 + row) * K + k0 + c8);
            }
            CP_COMMIT();
        }

        const __half* as = As[cur];
        const __half* bs = Bs[cur];
#pragma unroll
        for (int kc = 0; kc < 2; kc++) {
            uint32_t bfr[8][2];
#pragma unroll
            for (int nf = 0; nf < 8; nf++) {
                const __half* bp = bs + (wn + nf * 8 + qg) * LDH + kc * 16 + 2 * qc;
                bfr[nf][0] = *(const uint32_t*)(bp);
                bfr[nf][1] = *(const uint32_t*)(bp + 8);
            }
#pragma unroll
            for (int mf = 0; mf < 4; mf++) {
                const __half* ap = as + (wm + mf * 16 + qg) * LDH + kc * 16 + 2 * qc;
                uint32_t afr[4];
                afr[0] = *(const uint32_t*)(ap);
                afr[1] = *(const uint32_t*)(ap + 8 * LDH);
                afr[2] = *(const uint32_t*)(ap + 8);
                afr[3] = *(const uint32_t*)(ap + 8 * LDH + 8);
#pragma unroll
                for (int nf = 0; nf < 8; nf++)
                    mma_f16(acc[mf][nf], afr, bfr[nf], acc[mf][nf]);
            }
        }

        CP_WAIT0();
        __syncthreads();
    }

#pragma unroll
    for (int mf = 0; mf < 4; mf++) {
        int row0 = m0 + wm + mf * 16 + qg;
#pragma unroll
        for (int nf = 0; nf < 8; nf++) {
            int col = n0 + wn + nf * 8 + 2 * qc;
            float b0 = bias[col], b1 = bias[col + 1];
            float v00 = acc[mf][nf][0] + b0, v01 = acc[mf][nf][1] + b1;
            float v10 = acc[mf][nf][2] + b0, v11 = acc[mf][nf][3] + b1;
            if (qkv_round) {
                float sc = (col < D_MODEL) ? Q_PRESCALE : 1.0f;  // scale Q only
                __half* C = (__half*)Cv;
                *(__half2*)(C + (size_t)row0 * N + col) =
                    __floats2half2_rn(v00 * sc, v01 * sc);
                *(__half2*)(C + (size_t)(row0 + 8) * N + col) =
                    __floats2half2_rn(v10 * sc, v11 * sc);
            } else {
                float* C = (float*)Cv;
                *(float2*)(C + (size_t)row0 * N + col)       = make_float2(v00, v01);
                *(float2*)(C + (size_t)(row0 + 8) * N + col) = make_float2(v10, v11);
            }
        }
    }
}

// ---------------------------------------------------------------------------
// Flash attention, fp16 mma (m16n8k16), Br=128 / Bc=64 / Hd=64, 4 warps,
// 32 q-rows/warp -- R14 winner with ONE change: V B-fragments now come from
// ldmatrix.x4.trans (16 LDSM/warp-tile) instead of 128 scalar LDS.16 + 64
// packs. V stays row-major [k][n] in smem exactly as staged; .trans yields
// the m16n8k16 B fragment layout directly. Everything else byte-identical.
// ---------------------------------------------------------------------------
#define LDH_F 72
#define FLASH_SMEM ((64 * LDH_F + 64 * LDH_F + 128 * LDH_F) * 2)   // 36864 B

__global__ void __launch_bounds__(128, 2) flash_mma_kernel(
    const __half* __restrict__ qkv, __half* __restrict__ attn_out)
{
    extern __shared__ __half smh[];
    __half* Ks = smh;                            // [64][LDH_F]
    __half* Vs = smh + 64 * LDH_F;               // [64][LDH_F]
    __half* Ps = smh + 2 * 64 * LDH_F;           // [128][LDH_F] (Q staging, then P)

    const int tid  = threadIdx.x;
    const int lane = tid & 31;
    const int wid  = tid >> 5;
    const int qc   = lane & 3;
    const int qg   = lane >> 2;
    const int h    = blockIdx.y;
    const int q0   = blockIdx.x * 128;
    const int colb = h * HD;

    // ldmatrix.trans per-lane address for V B-frags:
    // matrix g: rows k + ((g&1)<<3) + l7, cols n + ((g>>1)<<3)
    // -> {r0,r1} = b0,b1 for even nt, {r2,r3} = b0,b1 for odd nt.
    const int g  = lane >> 3;
    const int l7 = lane & 7;
    const uint32_t v_lane_off =
        (uint32_t)(((((g & 1) << 3) + l7) * LDH_F + ((g >> 1) << 3)) * 2);
    const uint32_t vs_addr = smem_u32(Vs) + v_lane_off;

    // ---- Stage Q tile (pre-scaled, fp16): raw 16B copies into Ps ----
#pragma unroll
    for (int i = 0; i < 8; i++) {
        int id  = tid + i * 128;
        int row = id >> 3;
        int c8  = (id & 7) * 8;
        *(uint4*)(Ps + row * LDH_F + c8) =
            *(const uint4*)(qkv + (size_t)(q0 + row) * LDQKV + colb + c8);
    }
    __syncthreads();

    // ---- Q fragments to registers: 2 m-frags x 4 k16-chunks ----
    uint32_t qf[2][4][4];
#pragma unroll
    for (int mf = 0; mf < 2; mf++) {
        const int r0 = wid * 32 + mf * 16 + qg;
#pragma unroll
        for (int kc = 0; kc < 4; kc++) {
            const __half* qp = Ps + r0 * LDH_F + kc * 16 + 2 * qc;
            qf[mf][kc][0] = *(const uint32_t*)(qp);
            qf[mf][kc][1] = *(const uint32_t*)(qp + 8 * LDH_F);
            qf[mf][kc][2] = *(const uint32_t*)(qp + 8);
            qf[mf][kc][3] = *(const uint32_t*)(qp + 8 * LDH_F + 8);
        }
    }

    float o[2][8][4];
#pragma unroll
    for (int mf = 0; mf < 2; mf++)
#pragma unroll
        for (int nt = 0; nt < 8; nt++)
#pragma unroll
            for (int j = 0; j < 4; j++) o[mf][nt][j] = 0.0f;
    float m_run[2][2] = { {-CUDART_INF_F, -CUDART_INF_F},
                          {-CUDART_INF_F, -CUDART_INF_F} };
    float l_run[2][2] = { {0.f, 0.f}, {0.f, 0.f} };

    const int srow = tid >> 3;          // 0..15
    const int sc8  = (tid & 7) * 8;     // halves 0..56

    for (int k0 = 0; k0 < S_LEN; k0 += 64) {
        __syncthreads();   // prev tile reads done (covers Q-frag reads on t=0)
        // ---- Stage K, V tiles: raw LDG.128 -> STS.128 (L1-resident) ----
        {
            const __half* kb = qkv + (size_t)(k0 + srow) * LDQKV + colb + D_MODEL + sc8;
#pragma unroll
            for (int r = 0; r < 4; r++) {
                *(uint4*)(Ks + (srow + r * 16) * LDH_F + sc8) =
                    *(const uint4*)(kb + (size_t)(r * 16) * LDQKV);
                *(uint4*)(Vs + (srow + r * 16) * LDH_F + sc8) =
                    *(const uint4*)(kb + (size_t)(r * 16) * LDQKV + D_MODEL);
            }
        }
        __syncthreads();

        // ---- S = Q K^T, kc-outer: K B-frags loaded once, shared by both mf ----
        float s[2][8][4];
#pragma unroll
        for (int mf = 0; mf < 2; mf++)
#pragma unroll
            for (int nt = 0; nt < 8; nt++)
#pragma unroll
                for (int j = 0; j < 4; j++) s[mf][nt][j] = 0.0f;

#pragma unroll
        for (int kc = 0; kc < 4; kc++) {
            uint32_t bfr[8][2];
#pragma unroll
            for (int nt = 0; nt < 8; nt++) {
                const __half* kp = Ks + (nt * 8 + qg) * LDH_F + kc * 16 + 2 * qc;
                bfr[nt][0] = *(const uint32_t*)(kp);
                bfr[nt][1] = *(const uint32_t*)(kp + 8);
            }
#pragma unroll
            for (int mf = 0; mf < 2; mf++)
#pragma unroll
                for (int nt = 0; nt < 8; nt++)
                    mma_f16(s[mf][nt], qf[mf][kc], bfr[nt], s[mf][nt]);
        }

        // ---- Online softmax per m-fragment (exp2 domain), store P (fp16) ----
#pragma unroll
        for (int mf = 0; mf < 2; mf++) {
            const int r0 = wid * 32 + mf * 16 + qg;
            const int r1 = r0 + 8;

            float mlo = -CUDART_INF_F, mhi = -CUDART_INF_F;
#pragma unroll
            for (int nt = 0; nt < 8; nt++) {
                mlo = fmaxf(mlo, fmaxf(s[mf][nt][0], s[mf][nt][1]));
                mhi = fmaxf(mhi, fmaxf(s[mf][nt][2], s[mf][nt][3]));
            }
            mlo = fmaxf(mlo, __shfl_xor_sync(0xffffffffu, mlo, 1));
            mlo = fmaxf(mlo, __shfl_xor_sync(0xffffffffu, mlo, 2));
            mhi = fmaxf(mhi, __shfl_xor_sync(0xffffffffu, mhi, 1));
            mhi = fmaxf(mhi, __shfl_xor_sync(0xffffffffu, mhi, 2));

            float mnlo = fmaxf(m_run[mf][0], mlo);
            float mnhi = fmaxf(m_run[mf][1], mhi);
            float alo  = ex2f(m_run[mf][0] - mnlo);   // 0 on first tile
            float ahi  = ex2f(m_run[mf][1] - mnhi);
            m_run[mf][0] = mnlo; m_run[mf][1] = mnhi;

            float tlo = 0.0f, thi = 0.0f;
#pragma unroll
            for (int nt = 0; nt < 8; nt++) {
                float p0 = ex2f(s[mf][nt][0] - mnlo);
                float p1 = ex2f(s[mf][nt][1] - mnlo);
                float p2 = ex2f(s[mf][nt][2] - mnhi);
                float p3 = ex2f(s[mf][nt][3] - mnhi);
                tlo += p0 + p1;
                thi += p2 + p3;
                *(__half2*)(Ps + r0 * LDH_F + nt * 8 + 2 * qc) = __floats2half2_rn(p0, p1);
                *(__half2*)(Ps + r1 * LDH_F + nt * 8 + 2 * qc) = __floats2half2_rn(p2, p3);
            }
            tlo += __shfl_xor_sync(0xffffffffu, tlo, 1);
            tlo += __shfl_xor_sync(0xffffffffu, tlo, 2);
            thi += __shfl_xor_sync(0xffffffffu, thi, 1);
            thi += __shfl_xor_sync(0xffffffffu, thi, 2);
            l_run[mf][0] = l_run[mf][0] * alo + tlo;
            l_run[mf][1] = l_run[mf][1] * ahi + thi;

#pragma unroll
            for (int nt = 0; nt < 8; nt++) {
                o[mf][nt][0] *= alo; o[mf][nt][1] *= alo;
                o[mf][nt][2] *= ahi; o[mf][nt][3] *= ahi;
            }
        }

        __syncwarp();   // P rows are warp-private; order STS before LDS

        // ---- O += P V  (kc-outer; V B-frags via ldmatrix.x4.trans) ----
#pragma unroll
        for (int kc = 0; kc < 4; kc++) {
            uint32_t vfr[8][2];
#pragma unroll
            for (int ntp = 0; ntp < 4; ntp++)
                ldsm_x4_t(vfr[2 * ntp][0], vfr[2 * ntp][1],
                          vfr[2 * ntp + 1][0], vfr[2 * ntp + 1][1],
                          vs_addr + (uint32_t)((kc * 16 * LDH_F + ntp * 16) * 2));
#pragma unroll
            for (int mf = 0; mf < 2; mf++) {
                const int r0 = wid * 32 + mf * 16 + qg;
                const __half* pp = Ps + r0 * LDH_F + kc * 16 + 2 * qc;
                uint32_t a[4];
                a[0] = *(const uint32_t*)(pp);
                a[1] = *(const uint32_t*)(pp + 8 * LDH_F);
                a[2] = *(const uint32_t*)(pp + 8);
                a[3] = *(const uint32_t*)(pp + 8 * LDH_F + 8);
#pragma unroll
                for (int nt = 0; nt < 8; nt++)
                    mma_f16(o[mf][nt], a, vfr[nt], o[mf][nt]);
            }
        }
    }

    // ---- Epilogue: normalize, store fp16 attn ----
#pragma unroll
    for (int mf = 0; mf < 2; mf++) {
        const int r0 = wid * 32 + mf * 16 + qg;
        const int r1 = r0 + 8;
        float ilo = 1.0f / l_run[mf][0];
        float ihi = 1.0f / l_run[mf][1];
#pragma unroll
        for (int nt = 0; nt < 8; nt++) {
            *(__half2*)(attn_out + (size_t)(q0 + r0) * D_MODEL + colb + nt * 8 + 2 * qc) =
                __floats2half2_rn(o[mf][nt][0] * ilo, o[mf][nt][1] * ilo);
            *(__half2*)(attn_out + (size_t)(q0 + r1) * D_MODEL + colb + nt * 8 + 2 * qc) =
                __floats2half2_rn(o[mf][nt][2] * ihi, o[mf][nt][3] * ihi);
        }
    }
}

// ---------------------------------------------------------------------------
// Launch: round-to-fp16 -> QKV proj -> flash -> out proj
// ---------------------------------------------------------------------------
extern "C" void kernel_launch(void* const* d_in, const int* in_sizes, int n_in,
                              void* d_out, int out_size)
{
    const float* query = (const float*)d_in[0];   // [1,4096,512]
    const float* w_in  = (const float*)d_in[1];   // [1536,512]
    const float* b_in  = (const float*)d_in[2];   // [1536]
    const float* w_out = (const float*)d_in[3];   // [512,512]
    const float* b_out = (const float*)d_in[4];   // [512]
    float*       out   = (float*)d_out;           // [1,4096,512]

    __half *qkv, *attn, *qr, *wi, *wo;
    cudaGetSymbolAddress((void**)&qkv,  g_qkv);
    cudaGetSymbolAddress((void**)&attn, g_attn);
    cudaGetSymbolAddress((void**)&qr,   g_qr);
    cudaGetSymbolAddress((void**)&wi,   g_wi);
    cudaGetSymbolAddress((void**)&wo,   g_wo);

    cudaFuncSetAttribute(gemm_f16_bias,
                         cudaFuncAttributeMaxDynamicSharedMemorySize, GEMM_SMEM);
    cudaFuncSetAttribute(flash_mma_kernel,
                         cudaFuncAttributeMaxDynamicSharedMemorySize, FLASH_SMEM);

    // 0) Round inputs to fp16
    {
        int nq = S_LEN * D_MODEL / 4;          // 524288
        int ni = 3 * D_MODEL * D_MODEL / 4;    // 196608
        int no = D_MODEL * D_MODEL / 4;        // 65536
        round_f16_kernel<<<(nq + 255) / 256, 256>>>(query, qr, nq);
        round_f16_kernel<<<(ni + 255) / 256, 256>>>(w_in,  wi, ni);
        round_f16_kernel<<<(no + 255) / 256, 256>>>(w_out, wo, no);
    }

    // 1) QKV projection (+ Q pre-scale incl. log2e; fp16 output)
    {
        dim3 grid(LDQKV / 128, S_LEN / 128);   // (12, 32)
        gemm_f16_bias<<<grid, 128, GEMM_SMEM>>>(qr, wi, b_in, qkv,
                                                S_LEN, LDQKV, D_MODEL, 1);
    }

    // 2) Flash attention per head (fp16 m16n8k16, V via ldmatrix.trans)
    {
        dim3 grid(S_LEN / 128, H_NUM);   // (32, 8) = 256 CTAs
        flash_mma_kernel<<<grid, 128, FLASH_SMEM>>>(qkv, attn);
    }

    // 3) Output projection (fp32 output)
    {
        dim3 grid(D_MODEL / 128, S_LEN / 128);  // (4, 32)
        gemm_f16_bias<<<grid, 128, GEMM_SMEM>>>(attn, wo, b_out, out,
                                                S_LEN, D_MODEL, D_MODEL, 0);
    }
}